// round 10
// baseline (speedup 1.0000x reference)
#include <cuda_runtime.h>
#include <cuda_bf16.h>
#include <cstdint>

#define ULL unsigned long long

// ---------------------------------------------------------------------------
// Packed f32x2 helpers.
// ---------------------------------------------------------------------------
__device__ __forceinline__ ULL dup2(float v) {
    ULL r; asm("mov.b64 %0, {%1, %1};" : "=l"(r) : "f"(v)); return r;
}
__device__ __forceinline__ ULL pk2(float lo, float hi) {
    ULL r; asm("mov.b64 %0, {%1, %2};" : "=l"(r) : "f"(lo), "f"(hi)); return r;
}
__device__ __forceinline__ void fma2(ULL& d, ULL a, ULL b) {
    asm("fma.rn.f32x2 %0, %1, %2, %0;" : "+l"(d) : "l"(a), "l"(b));
}
__device__ __forceinline__ void unpk(ULL v, float& lo, float& hi) {
    asm("mov.b64 {%0, %1}, %2;" : "=f"(lo), "=f"(hi) : "l"(v));
}

__device__ __forceinline__ float tanh_f(float x) {
    return __fdividef(2.0f, 1.0f + __expf(-2.0f * x)) - 1.0f;
}

// ---------------------------------------------------------------------------
// Problem constants
// ---------------------------------------------------------------------------
static constexpr int B = 1024;
static constexpr int T = 512;

// Scratch (allocation-free per harness rules)
__device__ float g_y0[(size_t)B * T * 128];   // layer-0 output [b][t][dir*64+k]
__device__ float g_hcat[(size_t)B * 128];     // final hidden [hT_f, hT_b]

// Activation-row stride in ULLs (pad: conflict-free broadcasts, cheap stores)
static constexpr int AS = 18;

// ---------------------------------------------------------------------------
// Kernel 1: layer-0 bidirectional LSTM, gate-split layout.
// block=256: thread (gh=tid&1, j=(tid>>1)&63, pg=tid>>7) owns gate-pair gh
// (0:{i,f} 1:{g,o}) of hidden unit j for 8 batch rows (group pg). After the
// K-loop, gate halves exchange via shfl_xor(1); each thread finishes c/h for
// 4 rows. grid=(B/16, 2 dirs).
// ---------------------------------------------------------------------------
static constexpr int SMEM0 = 64 * 256 * 4 + 64 * AS * 8;   // 74752

__global__ void __launch_bounds__(256, 1) lstm0_kernel(
    const float* __restrict__ x,
    const float* __restrict__ WihF, const float* __restrict__ WhhF,
    const float* __restrict__ bihF, const float* __restrict__ bhhF,
    const float* __restrict__ WihB, const float* __restrict__ WhhB,
    const float* __restrict__ bihB, const float* __restrict__ bhhB)
{
    extern __shared__ float sm[];
    float* wt  = sm;                       // [64][256]
    ULL*   h_s = (ULL*)(sm + 64 * 256);    // [64][AS]

    const int dir = blockIdx.y;
    const int b0  = blockIdx.x * 16;
    const int tid = threadIdx.x;
    const int gh  = tid & 1;               // gate half
    const int j   = (tid >> 1) & 63;       // hidden unit
    const int pg  = tid >> 7;              // row group 0..1

    const float* Wih = dir ? WihB : WihF;
    const float* Whh = dir ? WhhB : WhhF;
    const float* bih = dir ? bihB : bihF;
    const float* bhh = dir ? bhhB : bhhF;

    // stage Whh transposed: wt[kk][j*4+g]
    for (int sidx = tid; sidx < 256 * 64; sidx += 256) {
        int gr = sidx >> 6, kk = sidx & 63;
        wt[kk * 256 + (gr & 63) * 4 + (gr >> 6)] = Whh[sidx];
    }
    const int gb = gh * 128;   // gate base: 0 -> i,f ; 128 -> g,o
    ULL wX[3];
    #pragma unroll
    for (int c = 0; c < 3; c++)
        wX[c] = pk2(Wih[(gb + j) * 3 + c], Wih[(gb + 64 + j) * 3 + c]);
    const ULL bias2 = pk2(bih[gb + j] + bhh[gb + j],
                          bih[gb + 64 + j] + bhh[gb + 64 + j]);

    for (int idx = tid; idx < 64 * AS; idx += 256) h_s[idx] = 0ULL;

    const float* xr[8];
    #pragma unroll
    for (int r = 0; r < 8; r++)
        xr[r] = x + (size_t)(b0 + 8 * pg + r) * 1536;

    const int dof = dir ? 64 : 0;
    float* yr[4];
    #pragma unroll
    for (int hr = 0; hr < 4; hr++) {
        int row = 8 * pg + gh * 4 + hr;
        yr[hr] = g_y0 + (size_t)(b0 + row) * (T * 128) + dof + j;
    }

    // branchless activation constants: s0 = mm * sigma(-km*a) + bb
    const float km = gh ? -2.0f : -1.0f;
    const float mm = gh ?  2.0f :  1.0f;
    const float bb = gh ? -1.0f :  0.0f;

    float cs[4] = {0.f, 0.f, 0.f, 0.f};
    const ULL* hp = h_s + pg * 8;
    __syncthreads();

    for (int s = 0; s < T; s++) {
        const int t = dir ? (T - 1 - s) : s;

        float xv[8][3];
        #pragma unroll
        for (int r = 0; r < 8; r++) {
            xv[r][0] = __ldg(xr[r] + t);
            xv[r][1] = __ldg(xr[r] + 512 + t);
            xv[r][2] = __ldg(xr[r] + 1024 + t);
        }

        ULL A[8];
        #pragma unroll
        for (int r = 0; r < 8; r++) A[r] = bias2;

        #pragma unroll 8
        for (int kk = 0; kk < 64; kk++) {
            ULL w = *(const ULL*)(wt + kk * 256 + j * 4 + gh * 2);
            ulonglong2 hv0 = *(const ulonglong2*)(hp + kk * AS);
            ulonglong2 hv1 = *(const ulonglong2*)(hp + kk * AS + 2);
            ulonglong2 hv2 = *(const ulonglong2*)(hp + kk * AS + 4);
            ulonglong2 hv3 = *(const ulonglong2*)(hp + kk * AS + 6);
            fma2(A[0], w, hv0.x);  fma2(A[1], w, hv0.y);
            fma2(A[2], w, hv1.x);  fma2(A[3], w, hv1.y);
            fma2(A[4], w, hv2.x);  fma2(A[5], w, hv2.y);
            fma2(A[6], w, hv3.x);  fma2(A[7], w, hv3.y);
        }
        #pragma unroll
        for (int r = 0; r < 8; r++) {
            #pragma unroll
            for (int c = 0; c < 3; c++)
                fma2(A[r], wX[c], dup2(xv[r][c]));
        }

        // activations for this gate-pair, all 8 rows
        float s0[8], s1[8];
        #pragma unroll
        for (int r = 0; r < 8; r++) {
            float a0, a1;
            unpk(A[r], a0, a1);
            s0[r] = fmaf(mm, __fdividef(1.0f, 1.0f + __expf(km * a0)), bb);
            s1[r] = __fdividef(1.0f, 1.0f + __expf(-a1));
        }
        // exchange with partner gate-half
        float pv0[8], pv1[8];
        #pragma unroll
        for (int r = 0; r < 8; r++) {
            pv0[r] = __shfl_xor_sync(0xffffffffu, s0[r], 1);
            pv1[r] = __shfl_xor_sync(0xffffffffu, s1[r], 1);
        }

        float hh[4];
        #pragma unroll
        for (int hr = 0; hr < 4; hr++) {
            float iv = gh ? pv0[4 + hr] : s0[hr];
            float fv = gh ? pv1[4 + hr] : s1[hr];
            float gv = gh ? s0[4 + hr]  : pv0[hr];
            float ov = gh ? s1[4 + hr]  : pv1[hr];
            cs[hr] = fv * cs[hr] + iv * gv;
            hh[hr] = ov * tanh_f(cs[hr]);
            yr[hr][(size_t)t * 128] = hh[hr];
        }

        __syncthreads();   // all h_s reads of this step complete
        {
            ULL* hw = h_s + j * AS + pg * 8 + gh * 4;
            *(ulonglong2*)(hw)     = make_ulonglong2(dup2(hh[0]), dup2(hh[1]));
            *(ulonglong2*)(hw + 2) = make_ulonglong2(dup2(hh[2]), dup2(hh[3]));
        }
        __syncthreads();   // h(t+1) visible
    }
}

// ---------------------------------------------------------------------------
// Kernel 2: layer-1 bidirectional LSTM, input GEMM (K=128) fused, gate-split.
// Same thread layout as lstm0. Combined weight panel wt[0..127]=Wih1^T,
// wt[128..191]=Whh1^T in shared. y0 register-prefetched across the K-loop.
// grid=(B/16, 2) = 128 CTAs.
// ---------------------------------------------------------------------------
static constexpr int SMEM1 = 192 * 256 * 4 + 128 * AS * 8 + 64 * AS * 8; // 224256

__global__ void __launch_bounds__(256, 1) lstm1_kernel(
    const float* __restrict__ WihF, const float* __restrict__ WhhF,
    const float* __restrict__ bihF, const float* __restrict__ bhhF,
    const float* __restrict__ WihB, const float* __restrict__ WhhB,
    const float* __restrict__ bihB, const float* __restrict__ bhhB)
{
    extern __shared__ float sm[];
    float* wt  = sm;                              // [192][256]
    ULL*   y_s = (ULL*)(sm + 192 * 256);          // [128 kk][AS]
    ULL*   h_s = y_s + 128 * AS;                  // [64 kk][AS]

    const int dir = blockIdx.y;
    const int b0  = blockIdx.x * 16;
    const int tid = threadIdx.x;
    const int gh  = tid & 1;
    const int j   = (tid >> 1) & 63;
    const int pg  = tid >> 7;

    const float* Wih = dir ? WihB : WihF;
    const float* Whh = dir ? WhhB : WhhF;
    const float* bih = dir ? bihB : bihF;
    const float* bhh = dir ? bhhB : bhhF;

    for (int sidx = tid; sidx < 256 * 128; sidx += 256) {
        int gr = sidx >> 7, kk = sidx & 127;
        wt[kk * 256 + (gr & 63) * 4 + (gr >> 6)] = Wih[sidx];
    }
    for (int sidx = tid; sidx < 256 * 64; sidx += 256) {
        int gr = sidx >> 6, kk = sidx & 63;
        wt[(128 + kk) * 256 + (gr & 63) * 4 + (gr >> 6)] = Whh[sidx];
    }
    const int gb = gh * 128;
    const ULL bias2 = pk2(bih[gb + j] + bhh[gb + j],
                          bih[gb + 64 + j] + bhh[gb + 64 + j]);

    for (int idx = tid; idx < 64 * AS; idx += 256) h_s[idx] = 0ULL;

    // y-fill role: row frow = tid>>4 (0..15), feats (tid&15) + 16*i, i=0..7
    const int frow = tid >> 4;
    const int flo  = tid & 15;
    const float* ybase = g_y0 + (size_t)(b0 + frow) * (T * 128) + flo;

    const float km = gh ? -2.0f : -1.0f;
    const float mm = gh ?  2.0f :  1.0f;
    const float bb = gh ? -1.0f :  0.0f;

    float cs[4] = {0.f, 0.f, 0.f, 0.f};
    float hh[4] = {0.f, 0.f, 0.f, 0.f};
    const ULL* yp = y_s + pg * 8;
    const ULL* hp = h_s + pg * 8;
    const int dof = dir ? 64 : 0;

    // prefetch first step's y0
    float p[8];
    {
        int t0 = dir ? T - 1 : 0;
        #pragma unroll
        for (int i = 0; i < 8; i++)
            p[i] = ybase[(size_t)t0 * 128 + 16 * i];
    }
    __syncthreads();

    for (int s = 0; s < T; s++) {
        // publish this step's y0, dup-packed
        #pragma unroll
        for (int i = 0; i < 8; i++)
            y_s[(16 * i + flo) * AS + frow] = dup2(p[i]);
        __syncthreads();   // y_s + h_s visible

        // prefetch next step's y0 (hidden under the K-loop)
        if (s + 1 < T) {
            int tn = dir ? (T - 2 - s) : (s + 1);
            #pragma unroll
            for (int i = 0; i < 8; i++)
                p[i] = ybase[(size_t)tn * 128 + 16 * i];
        }

        ULL A[8];
        #pragma unroll
        for (int r = 0; r < 8; r++) A[r] = bias2;

        #pragma unroll 8
        for (int kk = 0; kk < 128; kk++) {
            ULL w = *(const ULL*)(wt + kk * 256 + j * 4 + gh * 2);
            ulonglong2 yv0 = *(const ulonglong2*)(yp + kk * AS);
            ulonglong2 yv1 = *(const ulonglong2*)(yp + kk * AS + 2);
            ulonglong2 yv2 = *(const ulonglong2*)(yp + kk * AS + 4);
            ulonglong2 yv3 = *(const ulonglong2*)(yp + kk * AS + 6);
            fma2(A[0], w, yv0.x);  fma2(A[1], w, yv0.y);
            fma2(A[2], w, yv1.x);  fma2(A[3], w, yv1.y);
            fma2(A[4], w, yv2.x);  fma2(A[5], w, yv2.y);
            fma2(A[6], w, yv3.x);  fma2(A[7], w, yv3.y);
        }
        #pragma unroll 8
        for (int kk = 0; kk < 64; kk++) {
            ULL w = *(const ULL*)(wt + (128 + kk) * 256 + j * 4 + gh * 2);
            ulonglong2 hv0 = *(const ulonglong2*)(hp + kk * AS);
            ulonglong2 hv1 = *(const ulonglong2*)(hp + kk * AS + 2);
            ulonglong2 hv2 = *(const ulonglong2*)(hp + kk * AS + 4);
            ulonglong2 hv3 = *(const ulonglong2*)(hp + kk * AS + 6);
            fma2(A[0], w, hv0.x);  fma2(A[1], w, hv0.y);
            fma2(A[2], w, hv1.x);  fma2(A[3], w, hv1.y);
            fma2(A[4], w, hv2.x);  fma2(A[5], w, hv2.y);
            fma2(A[6], w, hv3.x);  fma2(A[7], w, hv3.y);
        }

        float s0[8], s1[8];
        #pragma unroll
        for (int r = 0; r < 8; r++) {
            float a0, a1;
            unpk(A[r], a0, a1);
            s0[r] = fmaf(mm, __fdividef(1.0f, 1.0f + __expf(km * a0)), bb);
            s1[r] = __fdividef(1.0f, 1.0f + __expf(-a1));
        }
        float pv0[8], pv1[8];
        #pragma unroll
        for (int r = 0; r < 8; r++) {
            pv0[r] = __shfl_xor_sync(0xffffffffu, s0[r], 1);
            pv1[r] = __shfl_xor_sync(0xffffffffu, s1[r], 1);
        }

        #pragma unroll
        for (int hr = 0; hr < 4; hr++) {
            float iv = gh ? pv0[4 + hr] : s0[hr];
            float fv = gh ? pv1[4 + hr] : s1[hr];
            float gv = gh ? s0[4 + hr]  : pv0[hr];
            float ov = gh ? s1[4 + hr]  : pv1[hr];
            cs[hr] = fv * cs[hr] + iv * gv;
            hh[hr] = ov * tanh_f(cs[hr]);
        }

        __syncthreads();   // all y_s/h_s reads of this step complete
        {
            ULL* hw = h_s + j * AS + pg * 8 + gh * 4;
            *(ulonglong2*)(hw)     = make_ulonglong2(dup2(hh[0]), dup2(hh[1]));
            *(ulonglong2*)(hw + 2) = make_ulonglong2(dup2(hh[2]), dup2(hh[3]));
        }
        // next iteration's y publish + barrier makes both visible
    }

    #pragma unroll
    for (int hr = 0; hr < 4; hr++) {
        int row = 8 * pg + gh * 4 + hr;
        g_hcat[(size_t)(b0 + row) * 128 + dof + j] = hh[hr];
    }
}

// ---------------------------------------------------------------------------
// Kernel 3: FC head. block = 256 = 4 rows x 64 fc1-outputs, grid = B/4.
// ---------------------------------------------------------------------------
__global__ void __launch_bounds__(256) head_kernel(
    const float* __restrict__ fc1W, const float* __restrict__ fc1b,
    const float* __restrict__ fc2W, const float* __restrict__ fc2b,
    float* __restrict__ out)
{
    __shared__ float f1[4][64];
    const int j = threadIdx.x;
    const int r = j >> 6;
    const int o = j & 63;
    const int b = blockIdx.x * 4 + r;

    const float* h = g_hcat + (size_t)b * 128;
    const float* w = fc1W + o * 128;
    float acc = fc1b[o];
    #pragma unroll 8
    for (int kk = 0; kk < 128; kk++) acc += w[kk] * h[kk];
    f1[r][o] = fmaxf(acc, 0.0f);
    __syncthreads();

    if (o < 2) {
        float a = fc2b[o];
        const float* w2 = fc2W + o * 64;
        #pragma unroll 8
        for (int kk = 0; kk < 64; kk++) a += w2[kk] * f1[r][kk];
        out[(size_t)b * 2 + o] = a;
    }
}

// ---------------------------------------------------------------------------
// Launcher
// ---------------------------------------------------------------------------
extern "C" void kernel_launch(void* const* d_in, const int* in_sizes, int n_in,
                              void* d_out, int out_size)
{
    const float* x      = (const float*)d_in[0];
    const float* Wih0f  = (const float*)d_in[1];
    const float* Whh0f  = (const float*)d_in[2];
    const float* bih0f  = (const float*)d_in[3];
    const float* bhh0f  = (const float*)d_in[4];
    const float* Wih0b  = (const float*)d_in[5];
    const float* Whh0b  = (const float*)d_in[6];
    const float* bih0b  = (const float*)d_in[7];
    const float* bhh0b  = (const float*)d_in[8];
    const float* Wih1f  = (const float*)d_in[9];
    const float* Whh1f  = (const float*)d_in[10];
    const float* bih1f  = (const float*)d_in[11];
    const float* bhh1f  = (const float*)d_in[12];
    const float* Wih1b  = (const float*)d_in[13];
    const float* Whh1b  = (const float*)d_in[14];
    const float* bih1b  = (const float*)d_in[15];
    const float* bhh1b  = (const float*)d_in[16];
    const float* fc1W   = (const float*)d_in[17];
    const float* fc1b   = (const float*)d_in[18];
    const float* fc2W   = (const float*)d_in[19];
    const float* fc2b   = (const float*)d_in[20];
    float* out = (float*)d_out;

    cudaFuncSetAttribute(lstm0_kernel,
                         cudaFuncAttributeMaxDynamicSharedMemorySize, SMEM0);
    cudaFuncSetAttribute(lstm1_kernel,
                         cudaFuncAttributeMaxDynamicSharedMemorySize, SMEM1);

    dim3 grid(B / 16, 2);
    lstm0_kernel<<<grid, 256, SMEM0>>>(x,
                                       Wih0f, Whh0f, bih0f, bhh0f,
                                       Wih0b, Whh0b, bih0b, bhh0b);

    lstm1_kernel<<<grid, 256, SMEM1>>>(Wih1f, Whh1f, bih1f, bhh1f,
                                       Wih1b, Whh1b, bih1b, bhh1b);

    head_kernel<<<B / 4, 256>>>(fc1W, fc1b, fc2W, fc2b, out);
}

// round 11
// speedup vs baseline: 1.4052x; 1.4052x over previous
#include <cuda_runtime.h>
#include <cuda_bf16.h>
#include <cstdint>

#define ULL unsigned long long

// ---------------------------------------------------------------------------
// Packed f32x2 helpers.
// ---------------------------------------------------------------------------
__device__ __forceinline__ ULL dup2(float v) {
    ULL r; asm("mov.b64 %0, {%1, %1};" : "=l"(r) : "f"(v)); return r;
}
__device__ __forceinline__ ULL pk2(float lo, float hi) {
    ULL r; asm("mov.b64 %0, {%1, %2};" : "=l"(r) : "f"(lo), "f"(hi)); return r;
}
__device__ __forceinline__ void fma2(ULL& d, ULL a, ULL b) {
    asm("fma.rn.f32x2 %0, %1, %2, %0;" : "+l"(d) : "l"(a), "l"(b));
}
__device__ __forceinline__ void add2(ULL& d, ULL a) {
    asm("add.rn.f32x2 %0, %0, %1;" : "+l"(d) : "l"(a));
}
__device__ __forceinline__ void unpk(ULL v, float& lo, float& hi) {
    asm("mov.b64 {%0, %1}, %2;" : "=f"(lo), "=f"(hi) : "l"(v));
}

__device__ __forceinline__ float sig_f(float x) {
    return __fdividef(1.0f, 1.0f + __expf(-x));
}
__device__ __forceinline__ float tanh_f(float x) {
    return __fdividef(2.0f, 1.0f + __expf(-2.0f * x)) - 1.0f;
}

// ---------------------------------------------------------------------------
// Problem constants
// ---------------------------------------------------------------------------
static constexpr int B = 1024;
static constexpr int T = 512;

// Scratch (allocation-free per harness rules)
__device__ float g_y0[(size_t)B * T * 128];   // layer-0 output [b][t][dir*64+k]
__device__ float g_hcat[(size_t)B * 128];     // final hidden [hT_f, hT_b]

// Activation-row stride in ULLs
static constexpr int AS = 18;

// ---------------------------------------------------------------------------
// Kernel 1: layer-0 bidirectional LSTM, K-split.
// block=256: thread (j=tid&63, pg=(tid>>6)&1, kh=tid>>7). Thread computes
// PARTIAL gate preacts over kk in [kh*32, kh*32+32) for 8 rows (group pg);
// partials for the non-owned 4 rows are exchanged through shared; each thread
// finishes rows 8pg+4kh .. +3 (adds bias + x, activations, c/h update).
// grid=(B/16, 2 dirs) = 128 CTAs.
// ---------------------------------------------------------------------------
static constexpr int SMEM0 = 64 * 256 * 4 + 64 * AS * 8 + 4 * 256 * 16; // 91136

__global__ void __launch_bounds__(256, 1) lstm0_kernel(
    const float* __restrict__ x,
    const float* __restrict__ WihF, const float* __restrict__ WhhF,
    const float* __restrict__ bihF, const float* __restrict__ bhhF,
    const float* __restrict__ WihB, const float* __restrict__ WhhB,
    const float* __restrict__ bihB, const float* __restrict__ bhhB)
{
    extern __shared__ float sm[];
    float*      wt  = sm;                         // [64][256]
    ULL*        h_s = (ULL*)(sm + 64 * 256);      // [64][AS]
    ulonglong2* red = (ulonglong2*)(h_s + 64 * AS);  // [4][256]

    const int dir = blockIdx.y;
    const int b0  = blockIdx.x * 16;
    const int tid = threadIdx.x;
    const int j   = tid & 63;
    const int pg  = (tid >> 6) & 1;
    const int kh  = tid >> 7;            // K half

    const float* Wih = dir ? WihB : WihF;
    const float* Whh = dir ? WhhB : WhhF;
    const float* bih = dir ? bihB : bihF;
    const float* bhh = dir ? bhhB : bhhF;

    // stage Whh transposed: wt[kk][j*4+g]
    for (int sidx = tid; sidx < 256 * 64; sidx += 256) {
        int gr = sidx >> 6, kk = sidx & 63;
        wt[kk * 256 + (gr & 63) * 4 + (gr >> 6)] = Whh[sidx];
    }
    ULL wA[3], wB[3];
    #pragma unroll
    for (int c = 0; c < 3; c++) {
        wA[c] = pk2(Wih[j * 3 + c],         Wih[(64 + j) * 3 + c]);
        wB[c] = pk2(Wih[(128 + j) * 3 + c], Wih[(192 + j) * 3 + c]);
    }
    const ULL biasA = pk2(bih[j] + bhh[j],             bih[64 + j] + bhh[64 + j]);
    const ULL biasB = pk2(bih[128 + j] + bhh[128 + j], bih[192 + j] + bhh[192 + j]);

    for (int idx = tid; idx < 64 * AS; idx += 256) h_s[idx] = 0ULL;

    // finishing rows: 8*pg + 4*kh + i
    const float* xr[4];
    float*       yr[4];
    const int dof = dir ? 64 : 0;
    #pragma unroll
    for (int i = 0; i < 4; i++) {
        int row = 8 * pg + 4 * kh + i;
        xr[i] = x + (size_t)(b0 + row) * 1536;
        yr[i] = g_y0 + (size_t)(b0 + row) * (T * 128) + dof + j;
    }

    float cs[4] = {0.f, 0.f, 0.f, 0.f};
    float hh[4] = {0.f, 0.f, 0.f, 0.f};
    const ULL* hp = h_s + pg * 8;
    const int kb = kh * 32;
    __syncthreads();

    for (int s = 0; s < T; s++) {
        const int t = dir ? (T - 1 - s) : s;

        float xv[4][3];
        #pragma unroll
        for (int i = 0; i < 4; i++) {
            xv[i][0] = __ldg(xr[i] + t);
            xv[i][1] = __ldg(xr[i] + 512 + t);
            xv[i][2] = __ldg(xr[i] + 1024 + t);
        }

        ULL A0[8], A1[8];
        #pragma unroll
        for (int r = 0; r < 8; r++) {
            bool own = (r >> 2) == kh;
            A0[r] = own ? biasA : 0ULL;
            A1[r] = own ? biasB : 0ULL;
        }

        #pragma unroll 8
        for (int kk2 = 0; kk2 < 32; kk2++) {
            int kk = kb + kk2;
            ulonglong2 w2  = *(const ulonglong2*)(wt + kk * 256 + j * 4);
            ulonglong2 hv0 = *(const ulonglong2*)(hp + kk * AS);
            ulonglong2 hv1 = *(const ulonglong2*)(hp + kk * AS + 2);
            ulonglong2 hv2 = *(const ulonglong2*)(hp + kk * AS + 4);
            ulonglong2 hv3 = *(const ulonglong2*)(hp + kk * AS + 6);
            fma2(A0[0], w2.x, hv0.x);  fma2(A1[0], w2.y, hv0.x);
            fma2(A0[1], w2.x, hv0.y);  fma2(A1[1], w2.y, hv0.y);
            fma2(A0[2], w2.x, hv1.x);  fma2(A1[2], w2.y, hv1.x);
            fma2(A0[3], w2.x, hv1.y);  fma2(A1[3], w2.y, hv1.y);
            fma2(A0[4], w2.x, hv2.x);  fma2(A1[4], w2.y, hv2.x);
            fma2(A0[5], w2.x, hv2.y);  fma2(A1[5], w2.y, hv2.y);
            fma2(A0[6], w2.x, hv3.x);  fma2(A1[6], w2.y, hv3.x);
            fma2(A0[7], w2.x, hv3.y);  fma2(A1[7], w2.y, hv3.y);
        }
        __syncthreads();   // B: all h_s reads done

        // store partials for the non-owned 4 rows to partner's slot
        if (kh == 0) {
            #pragma unroll
            for (int i = 0; i < 4; i++)
                red[i * 256 + (tid ^ 128)] = make_ulonglong2(A0[4 + i], A1[4 + i]);
        } else {
            #pragma unroll
            for (int i = 0; i < 4; i++)
                red[i * 256 + (tid ^ 128)] = make_ulonglong2(A0[i], A1[i]);
        }
        __syncthreads();   // C: partials visible

        // gather own rows into const-indexed regs and add partner partials
        ULL B0[4], B1[4];
        if (kh == 0) {
            #pragma unroll
            for (int i = 0; i < 4; i++) { B0[i] = A0[i]; B1[i] = A1[i]; }
        } else {
            #pragma unroll
            for (int i = 0; i < 4; i++) { B0[i] = A0[4 + i]; B1[i] = A1[4 + i]; }
        }
        #pragma unroll
        for (int i = 0; i < 4; i++) {
            ulonglong2 q = red[i * 256 + tid];
            add2(B0[i], q.x);
            add2(B1[i], q.y);
        }

        // finish: x terms + activations + state update
        #pragma unroll
        for (int i = 0; i < 4; i++) {
            #pragma unroll
            for (int c = 0; c < 3; c++) {
                ULL xd = dup2(xv[i][c]);
                fma2(B0[i], wA[c], xd);
                fma2(B1[i], wB[c], xd);
            }
            float ai, af, ag, ao;
            unpk(B0[i], ai, af);
            unpk(B1[i], ag, ao);
            cs[i] = sig_f(af) * cs[i] + sig_f(ai) * tanh_f(ag);
            hh[i] = sig_f(ao) * tanh_f(cs[i]);
            yr[i][(size_t)t * 128] = hh[i];
        }

        // publish h (dup-packed) for next step
        {
            ULL* hw = h_s + j * AS + pg * 8 + 4 * kh;
            *(ulonglong2*)(hw)     = make_ulonglong2(dup2(hh[0]), dup2(hh[1]));
            *(ulonglong2*)(hw + 2) = make_ulonglong2(dup2(hh[2]), dup2(hh[3]));
        }
        __syncthreads();   // D: h(t+1) visible
    }
}

// ---------------------------------------------------------------------------
// Kernel 2: layer-1 bidirectional LSTM, input GEMM fused, K-split.
// Combined activation buffer act[0..127]=y0(t) dup'd, act[128..191]=h dup'd;
// combined weight panel wt[0..127]=Wih1^T, wt[128..191]=Whh1^T.
// kh=0 covers kk 0..95, kh=1 covers kk 96..191 — uniform K-loop.
// Reduction buffer ALIASES the y part of act (dead between syncs B and D).
// grid=(B/16, 2) = 128 CTAs.
// ---------------------------------------------------------------------------
static constexpr int SMEM1 = 192 * 256 * 4 + 192 * AS * 8;  // 196608+27648=224256

__global__ void __launch_bounds__(256, 1) lstm1_kernel(
    const float* __restrict__ WihF, const float* __restrict__ WhhF,
    const float* __restrict__ bihF, const float* __restrict__ bhhF,
    const float* __restrict__ WihB, const float* __restrict__ WhhB,
    const float* __restrict__ bihB, const float* __restrict__ bhhB)
{
    extern __shared__ float sm[];
    float*      wt  = sm;                          // [192][256]
    ULL*        act = (ULL*)(sm + 192 * 256);      // [192][AS]: y then h
    ULL*        h_s = act + 128 * AS;
    ulonglong2* red = (ulonglong2*)act;            // aliases y region (16KB<=18.4KB)

    const int dir = blockIdx.y;
    const int b0  = blockIdx.x * 16;
    const int tid = threadIdx.x;
    const int j   = tid & 63;
    const int pg  = (tid >> 6) & 1;
    const int kh  = tid >> 7;

    const float* Wih = dir ? WihB : WihF;
    const float* Whh = dir ? WhhB : WhhF;
    const float* bih = dir ? bihB : bihF;
    const float* bhh = dir ? bhhB : bhhF;

    for (int sidx = tid; sidx < 256 * 128; sidx += 256) {
        int gr = sidx >> 7, kk = sidx & 127;
        wt[kk * 256 + (gr & 63) * 4 + (gr >> 6)] = Wih[sidx];
    }
    for (int sidx = tid; sidx < 256 * 64; sidx += 256) {
        int gr = sidx >> 6, kk = sidx & 63;
        wt[(128 + kk) * 256 + (gr & 63) * 4 + (gr >> 6)] = Whh[sidx];
    }
    const ULL biasA = pk2(bih[j] + bhh[j],             bih[64 + j] + bhh[64 + j]);
    const ULL biasB = pk2(bih[128 + j] + bhh[128 + j], bih[192 + j] + bhh[192 + j]);

    for (int idx = tid; idx < 64 * AS; idx += 256) h_s[idx] = 0ULL;

    // y-fill role: row frow = tid>>4 (0..15), feats (tid&15) + 16*i, i<8
    const int frow = tid >> 4;
    const int flo  = tid & 15;
    const float* ybase = g_y0 + (size_t)(b0 + frow) * (T * 128) + flo;

    float cs[4] = {0.f, 0.f, 0.f, 0.f};
    float hh[4] = {0.f, 0.f, 0.f, 0.f};
    const ULL* ap = act + pg * 8;
    const int kb = kh * 96;
    const int dof = dir ? 64 : 0;

    // prefetch first step's y0
    float p[8];
    {
        int t0 = dir ? T - 1 : 0;
        #pragma unroll
        for (int i = 0; i < 8; i++)
            p[i] = ybase[(size_t)t0 * 128 + 16 * i];
    }
    __syncthreads();

    for (int s = 0; s < T; s++) {
        // publish this step's y0 (dup-packed) into act[0..127]
        #pragma unroll
        for (int i = 0; i < 8; i++)
            act[(16 * i + flo) * AS + frow] = dup2(p[i]);
        __syncthreads();   // A: y + h visible

        // prefetch next step's y0 (hidden under the K-loop)
        if (s + 1 < T) {
            int tn = dir ? (T - 2 - s) : (s + 1);
            #pragma unroll
            for (int i = 0; i < 8; i++)
                p[i] = ybase[(size_t)tn * 128 + 16 * i];
        }

        ULL A0[8], A1[8];
        #pragma unroll
        for (int r = 0; r < 8; r++) {
            bool own = (r >> 2) == kh;
            A0[r] = own ? biasA : 0ULL;
            A1[r] = own ? biasB : 0ULL;
        }

        #pragma unroll 8
        for (int kk2 = 0; kk2 < 96; kk2++) {
            int kk = kb + kk2;
            ulonglong2 w2  = *(const ulonglong2*)(wt + kk * 256 + j * 4);
            ulonglong2 av0 = *(const ulonglong2*)(ap + kk * AS);
            ulonglong2 av1 = *(const ulonglong2*)(ap + kk * AS + 2);
            ulonglong2 av2 = *(const ulonglong2*)(ap + kk * AS + 4);
            ulonglong2 av3 = *(const ulonglong2*)(ap + kk * AS + 6);
            fma2(A0[0], w2.x, av0.x);  fma2(A1[0], w2.y, av0.x);
            fma2(A0[1], w2.x, av0.y);  fma2(A1[1], w2.y, av0.y);
            fma2(A0[2], w2.x, av1.x);  fma2(A1[2], w2.y, av1.x);
            fma2(A0[3], w2.x, av1.y);  fma2(A1[3], w2.y, av1.y);
            fma2(A0[4], w2.x, av2.x);  fma2(A1[4], w2.y, av2.x);
            fma2(A0[5], w2.x, av2.y);  fma2(A1[5], w2.y, av2.y);
            fma2(A0[6], w2.x, av3.x);  fma2(A1[6], w2.y, av3.x);
            fma2(A0[7], w2.x, av3.y);  fma2(A1[7], w2.y, av3.y);
        }
        __syncthreads();   // B: all act reads done (y region reusable as red)

        if (kh == 0) {
            #pragma unroll
            for (int i = 0; i < 4; i++)
                red[i * 256 + (tid ^ 128)] = make_ulonglong2(A0[4 + i], A1[4 + i]);
        } else {
            #pragma unroll
            for (int i = 0; i < 4; i++)
                red[i * 256 + (tid ^ 128)] = make_ulonglong2(A0[i], A1[i]);
        }
        __syncthreads();   // C: partials visible

        ULL B0[4], B1[4];
        if (kh == 0) {
            #pragma unroll
            for (int i = 0; i < 4; i++) { B0[i] = A0[i]; B1[i] = A1[i]; }
        } else {
            #pragma unroll
            for (int i = 0; i < 4; i++) { B0[i] = A0[4 + i]; B1[i] = A1[4 + i]; }
        }
        #pragma unroll
        for (int i = 0; i < 4; i++) {
            ulonglong2 q = red[i * 256 + tid];
            add2(B0[i], q.x);
            add2(B1[i], q.y);
        }

        #pragma unroll
        for (int i = 0; i < 4; i++) {
            float ai, af, ag, ao;
            unpk(B0[i], ai, af);
            unpk(B1[i], ag, ao);
            cs[i] = sig_f(af) * cs[i] + sig_f(ai) * tanh_f(ag);
            hh[i] = sig_f(ao) * tanh_f(cs[i]);
        }

        {
            ULL* hw = h_s + j * AS + pg * 8 + 4 * kh;
            *(ulonglong2*)(hw)     = make_ulonglong2(dup2(hh[0]), dup2(hh[1]));
            *(ulonglong2*)(hw + 2) = make_ulonglong2(dup2(hh[2]), dup2(hh[3]));
        }
        __syncthreads();   // D: red reads + h publish done before next y publish
    }

    #pragma unroll
    for (int i = 0; i < 4; i++) {
        int row = 8 * pg + 4 * kh + i;
        g_hcat[(size_t)(b0 + row) * 128 + dof + j] = hh[i];
    }
}

// ---------------------------------------------------------------------------
// Kernel 3: FC head. block = 256 = 4 rows x 64 fc1-outputs, grid = B/4.
// ---------------------------------------------------------------------------
__global__ void __launch_bounds__(256) head_kernel(
    const float* __restrict__ fc1W, const float* __restrict__ fc1b,
    const float* __restrict__ fc2W, const float* __restrict__ fc2b,
    float* __restrict__ out)
{
    __shared__ float f1[4][64];
    const int j = threadIdx.x;
    const int r = j >> 6;
    const int o = j & 63;
    const int b = blockIdx.x * 4 + r;

    const float* h = g_hcat + (size_t)b * 128;
    const float* w = fc1W + o * 128;
    float acc = fc1b[o];
    #pragma unroll 8
    for (int kk = 0; kk < 128; kk++) acc += w[kk] * h[kk];
    f1[r][o] = fmaxf(acc, 0.0f);
    __syncthreads();

    if (o < 2) {
        float a = fc2b[o];
        const float* w2 = fc2W + o * 64;
        #pragma unroll 8
        for (int kk = 0; kk < 64; kk++) a += w2[kk] * f1[r][kk];
        out[(size_t)b * 2 + o] = a;
    }
}

// ---------------------------------------------------------------------------
// Launcher
// ---------------------------------------------------------------------------
extern "C" void kernel_launch(void* const* d_in, const int* in_sizes, int n_in,
                              void* d_out, int out_size)
{
    const float* x      = (const float*)d_in[0];
    const float* Wih0f  = (const float*)d_in[1];
    const float* Whh0f  = (const float*)d_in[2];
    const float* bih0f  = (const float*)d_in[3];
    const float* bhh0f  = (const float*)d_in[4];
    const float* Wih0b  = (const float*)d_in[5];
    const float* Whh0b  = (const float*)d_in[6];
    const float* bih0b  = (const float*)d_in[7];
    const float* bhh0b  = (const float*)d_in[8];
    const float* Wih1f  = (const float*)d_in[9];
    const float* Whh1f  = (const float*)d_in[10];
    const float* bih1f  = (const float*)d_in[11];
    const float* bhh1f  = (const float*)d_in[12];
    const float* Wih1b  = (const float*)d_in[13];
    const float* Whh1b  = (const float*)d_in[14];
    const float* bih1b  = (const float*)d_in[15];
    const float* bhh1b  = (const float*)d_in[16];
    const float* fc1W   = (const float*)d_in[17];
    const float* fc1b   = (const float*)d_in[18];
    const float* fc2W   = (const float*)d_in[19];
    const float* fc2b   = (const float*)d_in[20];
    float* out = (float*)d_out;

    cudaFuncSetAttribute(lstm0_kernel,
                         cudaFuncAttributeMaxDynamicSharedMemorySize, SMEM0);
    cudaFuncSetAttribute(lstm1_kernel,
                         cudaFuncAttributeMaxDynamicSharedMemorySize, SMEM1);

    dim3 grid(B / 16, 2);
    lstm0_kernel<<<grid, 256, SMEM0>>>(x,
                                       Wih0f, Whh0f, bih0f, bhh0f,
                                       Wih0b, Whh0b, bih0b, bhh0b);

    lstm1_kernel<<<grid, 256, SMEM1>>>(Wih1f, Whh1f, bih1f, bhh1f,
                                       Wih1b, Whh1b, bih1b, bhh1b);

    head_kernel<<<B / 4, 256>>>(fc1W, fc1b, fc2W, fc2b, out);
}